// round 3
// baseline (speedup 1.0000x reference)
#include <cuda_runtime.h>
#include <cstdint>
#include <cstddef>

constexpr int Bn = 8, Tn = 4096, Mn = 1024;
constexpr int THREADS = 128;          // threads per block, each owns one float2 lane
constexpr int M2 = Mn / 2;            // 512 float2 per timestep
constexpr int CHUNKS = M2 / THREADS;  // 4 m-chunks
constexpr int STRIP = 128;            // timesteps per block
constexpr int NSTRIPS = Tn / STRIP;   // 32
constexpr float EPSF = 1e-6f;

// Bump-kernel taps K[d] = exp(1 - 1/(1 - (d/15)^2 + 1e-6)), d = 0..14
// (K[15] underflows to exactly 0 in f32). Evaluated in high precision offline;
// emitted as literals so ptxas uses the FFMA-imm form (rt=1, zero registers).
__device__ constexpr float TAP[15] = {
    1.00000100f, 0.99554666f, 0.98206428f, 0.95919015f, 0.92630340f,
    0.88249802f, 0.82656660f, 0.75698827f, 0.67198882f, 0.56978420f,
    0.44933042f, 0.31240435f, 0.16901461f, 0.04890669f, 0.00116090f};

// Prefix sums PSUM[j] = sum_{d<=j} K[d]  (row-normalizers for t = 0..15+)
__device__ constexpr float PSUM[16] = {
    1.00000100f, 1.99554766f, 2.97761194f, 3.93680209f, 4.86310549f,
    5.74560351f, 6.57217011f, 7.32915838f, 8.00114720f, 8.57093140f,
    9.02026182f, 9.33266617f, 9.50168078f, 9.55058747f, 9.55174837f,
    9.55174837f};

__global__ void __launch_bounds__(THREADS, 8)
bump_conv_kernel(const float2* __restrict__ x,
                 const float*  __restrict__ gate_raw,
                 float2*       __restrict__ out) {
    const int mp = blockIdx.x * THREADS + threadIdx.x;  // float2 lane in [0, 512)
    const int b  = blockIdx.z;
    const int t0 = blockIdx.y * STRIP;                  // multiple of 128 (t0 % 16 == 0)

    // per-channel gates (softplus); folded with the normalizer at the output
    const float g0 = log1pf(__expf(gate_raw[2 * mp]));
    const float g1 = log1pf(__expf(gate_raw[2 * mp + 1]));

    const float rS = 1.0f / fmaxf(PSUM[15], EPSF);  // steady-state 1/rowsum
    const float c0 = g0 * rS, c1 = g1 * rS;

    const size_t base = ((size_t)b * Tn + t0) * M2 + mp;
    const float2* xp = x + base;
    float2*       op = out + base;

    // sliding window of the last 16 inputs; all indices compile-time static
    float2 ring[16];
    if (t0 == 0) {
#pragma unroll
        for (int k = 0; k < 16; ++k) ring[k] = make_float2(0.f, 0.f);
    } else {
#pragma unroll
        for (int d = 0; d < 15; ++d)
            ring[15 - d] = xp[(ptrdiff_t)(-(1 + d)) * M2];  // x[t0-1-d] -> slot (t0-1-d)&15
        ring[0] = make_float2(0.f, 0.f);  // overwritten at t0 before any read
    }

    auto step = [&](int tOff, int j, float sx, float sy) {
        float2 v = xp[(tOff + j) * M2];
        float ax = TAP[0] * v.x;
        float ay = TAP[0] * v.y;
#pragma unroll
        for (int d = 1; d < 15; ++d) {                 // j, d compile-time
            ax = fmaf(TAP[d], ring[(j - d) & 15].x, ax);
            ay = fmaf(TAP[d], ring[(j - d) & 15].y, ay);
        }
        ring[j & 15] = v;
        __stcs(&op[(tOff + j) * M2], make_float2(ax * sx, ay * sy));
    };

    int itStart = 0;
    if (t0 == 0) {
        // boundary rows t = 0..15: per-row normalization 1/PSUM[t]
#pragma unroll
        for (int j = 0; j < 16; ++j) {
            float rj = 1.0f / fmaxf(PSUM[j], EPSF);
            step(0, j, g0 * rj, g1 * rj);
        }
        itStart = 1;
    }

#pragma unroll 1
    for (int it = itStart; it < STRIP / 16; ++it) {
#pragma unroll
        for (int j = 0; j < 16; ++j) step(it * 16, j, c0, c1);
    }
}

extern "C" void kernel_launch(void* const* d_in, const int* in_sizes, int n_in,
                              void* d_out, int out_size) {
    const float* x        = (const float*)d_in[0];
    // d_in[1] (mask) is exactly tril(ones); already encoded in the causal taps.
    const float* gate_raw = (const float*)d_in[2];

    dim3 grid(CHUNKS, NSTRIPS, Bn);
    bump_conv_kernel<<<grid, THREADS>>>((const float2*)x, gate_raw, (float2*)d_out);
}

// round 4
// speedup vs baseline: 1.2108x; 1.2108x over previous
#include <cuda_runtime.h>
#include <cstdint>
#include <cstddef>
#include <type_traits>

constexpr int Bn = 8, Tn = 4096, Mn = 1024;
constexpr int THREADS = 256;          // each thread owns one float2 lane
constexpr int M2 = Mn / 2;            // 512 float2 per timestep
constexpr int CHUNKS = M2 / THREADS;  // 2
constexpr int STRIP = 128;            // timesteps per block
constexpr int NSTRIPS = Tn / STRIP;   // 32
constexpr float EPSF = 1e-6f;

// Bump taps K[d] = exp(1 - 1/(1 - (d/15)^2 + 1e-6)), d=0..14 (K[15] == 0.0f in f32).
// Literals -> ptxas FFMA-imm form (rt_SMSP=1, zero tap registers).
__device__ constexpr float TAP[15] = {
    1.00000100f, 0.99554666f, 0.98206428f, 0.95919015f, 0.92630340f,
    0.88249802f, 0.82656660f, 0.75698827f, 0.67198882f, 0.56978420f,
    0.44933042f, 0.31240435f, 0.16901461f, 0.04890669f, 0.00116090f};

__device__ constexpr float PSUM[16] = {
    1.00000100f, 1.99554766f, 2.97761194f, 3.93680209f, 4.86310549f,
    5.74560351f, 6.57217011f, 7.32915838f, 8.00114720f, 8.57093140f,
    9.02026182f, 9.33266617f, 9.50168078f, 9.55058747f, 9.55174837f,
    9.55174837f};

__global__ void __launch_bounds__(THREADS)
bump_conv_kernel(const float2* __restrict__ x,
                 const float*  __restrict__ gate_raw,
                 float2*       __restrict__ out) {
    const int mp = blockIdx.x * THREADS + threadIdx.x;  // float2 lane in [0, 512)
    const int b  = blockIdx.z;
    const int t0 = blockIdx.y * STRIP;

    const float g0 = log1pf(__expf(gate_raw[2 * mp]));
    const float g1 = log1pf(__expf(gate_raw[2 * mp + 1]));
    const float rS = 1.0f / fmaxf(PSUM[15], EPSF);
    const float c0 = g0 * rS, c1 = g1 * rS;

    const size_t base = ((size_t)b * Tn + t0) * M2 + mp;
    const float2* xp = x + base;
    float2*       op = out + base;

    float2 A[16], B[16];  // double buffer: buf[j] = x[tb + j] for the group at base tb

    // Batch all 16 group loads back-to-back: explicit MLP=16 per warp.
    auto load16 = [&](float2 (&buf)[16], int tb) {
#pragma unroll
        for (int j = 0; j < 16; ++j) buf[j] = xp[(tb + j) * M2];
    };

    // Compute the 16 outputs of group tb. cur = group tb, prev = group tb-16.
    // out[tb+j] = sum_{d=0..14} TAP[d] * x[tb+j-d]; all indices compile-time.
    auto comp16 = [&](auto per_row, const float2 (&cur)[16],
                      const float2 (&prev)[16], int tb) {
#pragma unroll
        for (int j = 0; j < 16; ++j) {
            float ax = TAP[0] * cur[j].x;
            float ay = TAP[0] * cur[j].y;
#pragma unroll
            for (int d = 1; d < 15; ++d) {
                if (d <= j) {
                    ax = fmaf(TAP[d], cur[j - d].x, ax);
                    ay = fmaf(TAP[d], cur[j - d].y, ay);
                } else {
                    ax = fmaf(TAP[d], prev[16 + j - d].x, ax);
                    ay = fmaf(TAP[d], prev[16 + j - d].y, ay);
                }
            }
            float s0, s1;
            if constexpr (decltype(per_row)::value) {
                float rj = 1.0f / fmaxf(PSUM[j], EPSF);  // rows t=0..15
                s0 = g0 * rj; s1 = g1 * rj;
            } else {
                s0 = c0; s1 = c1;
            }
            op[(tb + j) * M2] = make_float2(ax * s0, ay * s1);
        }
    };

    if (t0 == 0) {
#pragma unroll
        for (int k = 0; k < 16; ++k) A[k] = make_float2(0.f, 0.f);
        load16(B, 0);
        comp16(std::true_type{}, B, A, 0);   // boundary rows: per-row normalizer
    } else {
        load16(A, -16);                      // halo: previous 16 timesteps
        load16(B, 0);
        comp16(std::false_type{}, B, A, 0);
    }
    load16(A, 16);
    comp16(std::false_type{}, A, B, 16);

#pragma unroll 1
    for (int g2 = 1; g2 < STRIP / 32; ++g2) {
        const int tb = 32 * g2;
        load16(B, tb);
        comp16(std::false_type{}, B, A, tb);
        load16(A, tb + 16);
        comp16(std::false_type{}, A, B, tb + 16);
    }
}

extern "C" void kernel_launch(void* const* d_in, const int* in_sizes, int n_in,
                              void* d_out, int out_size) {
    const float* x        = (const float*)d_in[0];
    // d_in[1] (mask) is exactly tril(ones); already encoded in the causal taps.
    const float* gate_raw = (const float*)d_in[2];

    dim3 grid(CHUNKS, NSTRIPS, Bn);
    bump_conv_kernel<<<grid, THREADS>>>((const float2*)x, gate_raw, (float2*)d_out);
}